// round 12
// baseline (speedup 1.0000x reference)
#include <cuda_runtime.h>
#include <cuda_bf16.h>
#include <stdint.h>
#include <math.h>

#define BB 8
#define CC 256
#define NN 4096
#define II 128
#define LOG2E 1.4426950408889634f
#define QK_SCALE 0.08838834764831845f   // 1/sqrt(128)

// ---------------- scratch (device globals: allocation-free contract) ----------
static __device__ __nv_bfloat16 g_wh[3*II*CC];           // bf16 weights [m][i][c]
static __device__ __nv_bfloat16 g_qh[(size_t)BB*NN*II];  // theta, pre-scaled by QK_SCALE*LOG2E
static __device__ __nv_bfloat16 g_kh[(size_t)BB*NN*II];  // phi
static __device__ __nv_bfloat16 g_vh[(size_t)BB*NN*II];  // g
static __device__ __nv_bfloat16 g_oh[(size_t)BB*NN*II];  // normalized attn out, bf16 [B,N,I]
static __device__ float g_out[(size_t)BB*CC*NN];         // projected [B,C,N]
static __device__ float g_sum[CC];
static __device__ float g_sumsq[CC];
static __device__ float g_pool[BB*CC];                   // raw channel sums of x
static __device__ float g_chw[BB*CC];
static __device__ float g_bns[CC];
static __device__ float g_bnb[CC];

// ---------------- PTX helpers -------------------------------------------------
__device__ __forceinline__ uint32_t smem_u32(const void* p) {
    return (uint32_t)__cvta_generic_to_shared(p);
}
__device__ __forceinline__ void ldsm_x4(uint32_t* r, uint32_t addr) {
    asm volatile("ldmatrix.sync.aligned.m8n8.x4.shared.b16 {%0,%1,%2,%3},[%4];"
                 : "=r"(r[0]), "=r"(r[1]), "=r"(r[2]), "=r"(r[3]) : "r"(addr));
}
__device__ __forceinline__ void ldsm_x4_t(uint32_t* r, uint32_t addr) {
    asm volatile("ldmatrix.sync.aligned.m8n8.x4.trans.shared.b16 {%0,%1,%2,%3},[%4];"
                 : "=r"(r[0]), "=r"(r[1]), "=r"(r[2]), "=r"(r[3]) : "r"(addr));
}
__device__ __forceinline__ void mma16816(float* d, const uint32_t* a, uint32_t b0, uint32_t b1) {
    asm volatile("mma.sync.aligned.m16n8k16.row.col.f32.bf16.bf16.f32 "
                 "{%0,%1,%2,%3},{%4,%5,%6,%7},{%8,%9},{%0,%1,%2,%3};"
                 : "+f"(d[0]), "+f"(d[1]), "+f"(d[2]), "+f"(d[3])
                 : "r"(a[0]), "r"(a[1]), "r"(a[2]), "r"(a[3]), "r"(b0), "r"(b1));
}
__device__ __forceinline__ float ex2(float x) {
    float y;
    asm("ex2.approx.f32 %0, %1;" : "=f"(y) : "f"(x));
    return y;
}
__device__ __forceinline__ void cp_async16(uint32_t saddr, const void* gaddr) {
    asm volatile("cp.async.cg.shared.global [%0], [%1], 16;" :: "r"(saddr), "l"(gaddr));
}
#define CP_COMMIT()  asm volatile("cp.async.commit_group;" ::: "memory")
#define CP_WAIT0()   asm volatile("cp.async.wait_group 0;" ::: "memory")

__device__ __forceinline__ int4 pack8_bf16(float4 a, float4 b, float sc) {
    __nv_bfloat162 h0 = __floats2bfloat162_rn(a.x*sc, a.y*sc);
    __nv_bfloat162 h1 = __floats2bfloat162_rn(a.z*sc, a.w*sc);
    __nv_bfloat162 h2 = __floats2bfloat162_rn(b.x*sc, b.y*sc);
    __nv_bfloat162 h3 = __floats2bfloat162_rn(b.z*sc, b.w*sc);
    int4 pk;
    pk.x = *(int*)&h0; pk.y = *(int*)&h1; pk.z = *(int*)&h2; pk.w = *(int*)&h3;
    return pk;
}

// ---------------- zero accumulators -------------------------------------------
__global__ void k_zero() {
    int t = threadIdx.x;
    g_sum[t] = 0.f;
    g_sumsq[t] = 0.f;
    #pragma unroll
    for (int i = 0; i < 8; i++) g_pool[t + i*256] = 0.f;
}

// ---------------- weight pre-conversion to bf16 --------------------------------
__global__ void k_prew(const float* __restrict__ tw, const float* __restrict__ pw,
                       const float* __restrict__ gw) {
    int idx = blockIdx.x * 256 + threadIdx.x;   // 12288 threads x 8 elems
    int m = idx / 4096;
    int e = (idx % 4096) * 8;
    const float* w = (m == 0) ? tw : (m == 1 ? pw : gw);
    float4 a = *(const float4*)&w[e];
    float4 b = *(const float4*)&w[e + 4];
    *(int4*)&g_wh[m*II*CC + e] = pack8_bf16(a, b, 1.0f);
}

// ---------------- fused projections + SE pooling -------------------------------
extern __shared__ int4 smp4[];

__global__ __launch_bounds__(256) void k_proj(const float* __restrict__ x) {
    int4* sX4 = smp4;                 // 4 chunks x (64 rows x 8 units)
    int4* sW4 = smp4 + 2048;          // 2 bufs x 1024 int4
    __nv_bfloat16* sT = (__nv_bfloat16*)(smp4 + 2048);  // aliases sW (dead after cc loop)

    int b  = blockIdx.z;
    int n0 = blockIdx.x * 64;
    int tid = threadIdx.x;
    int lane = tid & 31, warp = tid >> 5;

    #pragma unroll
    for (int p = 0; p < 8; p++) {
        int idx = tid + p*256;
        int cc  = idx >> 9;
        int wi  = idx & 511;
        int row = wi >> 3, u = wi & 7;
        const float* xp = x + ((size_t)b*CC + cc*64 + row)*NN + n0 + u*8;
        float4 a = *(const float4*)xp;
        float4 bv = *(const float4*)(xp + 4);
        sX4[cc*512 + row*8 + (u ^ (row & 7))] = pack8_bf16(a, bv, 1.0f);
        float ss = (a.x + a.y) + (a.z + a.w) + (bv.x + bv.y) + (bv.z + bv.w);
        ss += __shfl_xor_sync(0xffffffffu, ss, 1);
        ss += __shfl_xor_sync(0xffffffffu, ss, 2);
        ss += __shfl_xor_sync(0xffffffffu, ss, 4);
        if ((lane & 7) == 0) atomicAdd(&g_pool[b*CC + cc*64 + row], ss);
    }

    int rowA = 16*warp + (lane & 15);
    int rbase = lane & 15;
    int usel = (lane >> 4) & 1;
    int ir = 16*warp + (lane >> 2);
    int cb = (lane & 3) * 2;

    #pragma unroll 1
    for (int m = 0; m < 3; m++) {
        __nv_bfloat16* outp = (m == 0) ? g_qh : (m == 1 ? g_kh : g_vh);
        float qs = (m == 0) ? (QK_SCALE * LOG2E) : 1.0f;
        const __nv_bfloat16* wm = g_wh + m*II*CC;

        float acc[8][4];
        #pragma unroll
        for (int t = 0; t < 8; t++) { acc[t][0]=0.f; acc[t][1]=0.f; acc[t][2]=0.f; acc[t][3]=0.f; }

        #pragma unroll 1
        for (int cc = 0; cc < 4; cc++) {
            int buf = cc & 1;
            #pragma unroll
            for (int p = 0; p < 4; p++) {
                int idx = tid + p*256;
                int row = idx >> 3, u = idx & 7;
                sW4[buf*1024 + row*8 + (u ^ (row & 7))] =
                    *(const int4*)&wm[(size_t)row*CC + cc*64 + u*8];
            }
            __syncthreads();

            uint32_t aW[4][4];
            #pragma unroll
            for (int kc = 0; kc < 4; kc++) {
                int u = 2*kc + usel;
                ldsm_x4(aW[kc], smem_u32(sW4) +
                        (uint32_t)((buf*1024 + rowA*8 + (u ^ (rowA & 7))) * 16));
            }
            #pragma unroll
            for (int kc = 0; kc < 4; kc++) {
                int row = 16*kc + rbase;
                int sw = row & 7;
                #pragma unroll
                for (int nb = 0; nb < 4; nb++) {
                    int u = 2*nb + usel;
                    uint32_t bX[4];
                    ldsm_x4_t(bX, smem_u32(sX4) + (uint32_t)((cc*512 + row*8 + (u ^ sw)) * 16));
                    mma16816(acc[2*nb],   aW[kc], bX[0], bX[1]);
                    mma16816(acc[2*nb+1], aW[kc], bX[2], bX[3]);
                }
            }
        }

        __syncthreads();
        #pragma unroll
        for (int nb = 0; nb < 4; nb++) {
            #pragma unroll
            for (int h = 0; h < 2; h++) {
                int a = 2*nb + h;
                int nn = 16*nb + 8*h + cb;
                sT[nn*136 + ir]         = __float2bfloat16(acc[a][0]*qs);
                sT[(nn+1)*136 + ir]     = __float2bfloat16(acc[a][1]*qs);
                sT[nn*136 + ir + 8]     = __float2bfloat16(acc[a][2]*qs);
                sT[(nn+1)*136 + ir + 8] = __float2bfloat16(acc[a][3]*qs);
            }
        }
        __syncthreads();
        #pragma unroll
        for (int p = 0; p < 4; p++) {
            int idx = tid + p*256;
            int nn = idx >> 4, u = idx & 15;
            *(int4*)&outp[((size_t)b*NN + n0 + nn)*II + u*8] = *(int4*)&sT[nn*136 + u*8];
        }
        __syncthreads();
    }
}

// ---------------- flash attention: bf16 HMMA, BN=32, 3 CTAs/SM ----------------
// 64 queries/CTA, 4 warps x m16; 32-key tiles; softmax fused per 16-key chunk
// so MUFU/pack overlaps PV MMAs in-warp. smem 48KB -> 3 CTAs/SM: desynced CTAs
// fill each other's softmax bubbles on the tensor pipe.
extern __shared__ __nv_bfloat16 smh[];

__global__ __launch_bounds__(128, 3) void k_flash() {
    int4* sQ4 = (int4*)smh;                  // 64 rows x 16 units = 1024 int4
    int4* sK4 = (int4*)smh + 1024;           // 2 bufs x 512 int4 (32 rows)
    int4* sV4 = (int4*)smh + 2048;           // 2 bufs x 512 int4

    int b  = blockIdx.y;
    int q0 = blockIdx.x * 64;
    int tid = threadIdx.x;
    int lane = tid & 31, warp = tid >> 5;
    int qw = warp * 16;

    const __nv_bfloat16* kp = g_kh + (size_t)b*NN*II;
    const __nv_bfloat16* vp = g_vh + (size_t)b*NN*II;

    auto stage = [&](int buf, int kt) {
        const int4* kg = (const int4*)(kp + (size_t)(kt*32)*II);
        const int4* vg = (const int4*)(vp + (size_t)(kt*32)*II);
        uint32_t kb = smem_u32(sK4 + buf*512);
        uint32_t vb = smem_u32(sV4 + buf*512);
        #pragma unroll
        for (int p = 0; p < 4; p++) {
            int idx = tid + p*128;
            int row = idx >> 4, u = idx & 15;
            uint32_t d = (uint32_t)((row*16 + (u ^ (row & 7))) * 16);
            cp_async16(kb + d, kg + row*16 + u);
            cp_async16(vb + d, vg + row*16 + u);
        }
    };

    stage(0, 0);
    CP_COMMIT();

    {
        const int4* qg = (const int4*)(g_qh + ((size_t)b*NN + q0)*II);
        #pragma unroll
        for (int p = 0; p < 8; p++) {
            int idx = tid + p*128;
            int row = idx >> 4, u = idx & 15;
            sQ4[row*16 + (u ^ (row & 7))] = qg[row*16 + u];
        }
    }
    __syncthreads();

    uint32_t aQ[8][4];
    {
        int row = qw + (lane & 15);
        #pragma unroll
        for (int kc = 0; kc < 8; kc++) {
            int u = 2*kc + ((lane >> 4) & 1);
            uint32_t addr = smem_u32(sQ4) + (uint32_t)((row*16 + (u ^ (row & 7))) * 16);
            ldsm_x4(aQ[kc], addr);
        }
    }

    float O[16][4];
    #pragma unroll
    for (int t = 0; t < 16; t++) { O[t][0]=0.f; O[t][1]=0.f; O[t][2]=0.f; O[t][3]=0.f; }
    float ls_lo = 0.f, ls_hi = 0.f;

    int rowB = (lane & 7) + ((lane >> 4) & 1) * 8;
    int uBsel = (lane >> 3) & 1;
    int rowV = (lane & 15);
    int uVsel = (lane >> 4) & 1;

    for (int kt = 0; kt < 128; kt++) {
        int cur = kt & 1;
        CP_WAIT0();
        __syncthreads();

        if (kt < 127) {
            stage(cur ^ 1, kt + 1);
            CP_COMMIT();
        }

        uint32_t sKb = smem_u32(sK4 + cur*512);
        uint32_t sVb = smem_u32(sV4 + cur*512);

        // ---- S = Q K^T over this 32-key tile ----
        float S[4][4];
        #pragma unroll
        for (int j = 0; j < 4; j++) { S[j][0]=0.f; S[j][1]=0.f; S[j][2]=0.f; S[j][3]=0.f; }

        #pragma unroll
        for (int jp = 0; jp < 2; jp++) {
            int row = 16*jp + rowB;
            int sw = row & 7;
            #pragma unroll
            for (int kc = 0; kc < 8; kc++) {
                int u = 2*kc + uBsel;
                uint32_t bK[4];
                ldsm_x4(bK, sKb + (uint32_t)((row*16 + (u ^ sw)) * 16));
                mma16816(S[2*jp],   aQ[kc], bK[0], bK[1]);
                mma16816(S[2*jp+1], aQ[kc], bK[2], bK[3]);
            }
        }

        // ---- fused softmax-lite + PV per 16-key chunk ----
        #pragma unroll
        for (int kc2 = 0; kc2 < 2; kc2++) {
            float p00 = ex2(S[2*kc2][0]),   p01 = ex2(S[2*kc2][1]);
            float p02 = ex2(S[2*kc2][2]),   p03 = ex2(S[2*kc2][3]);
            float p10 = ex2(S[2*kc2+1][0]), p11 = ex2(S[2*kc2+1][1]);
            float p12 = ex2(S[2*kc2+1][2]), p13 = ex2(S[2*kc2+1][3]);
            ls_lo += (p00 + p01) + (p10 + p11);
            ls_hi += (p02 + p03) + (p12 + p13);
            __nv_bfloat162 h0 = __floats2bfloat162_rn(p00, p01);
            __nv_bfloat162 h1 = __floats2bfloat162_rn(p02, p03);
            __nv_bfloat162 h2 = __floats2bfloat162_rn(p10, p11);
            __nv_bfloat162 h3 = __floats2bfloat162_rn(p12, p13);
            uint32_t aP[4];
            aP[0] = *(uint32_t*)&h0;
            aP[1] = *(uint32_t*)&h1;
            aP[2] = *(uint32_t*)&h2;
            aP[3] = *(uint32_t*)&h3;

            int row = 16*kc2 + rowV;
            int sw = row & 7;
            #pragma unroll
            for (int nt2 = 0; nt2 < 8; nt2++) {
                int u = 2*nt2 + uVsel;
                uint32_t bV[4];
                ldsm_x4_t(bV, sVb + (uint32_t)((row*16 + (u ^ sw)) * 16));
                mma16816(O[2*nt2],   aP, bV[0], bV[1]);
                mma16816(O[2*nt2+1], aP, bV[2], bV[3]);
            }
        }
    }

    ls_lo += __shfl_xor_sync(0xffffffffu, ls_lo, 1);
    ls_lo += __shfl_xor_sync(0xffffffffu, ls_lo, 2);
    ls_hi += __shfl_xor_sync(0xffffffffu, ls_hi, 1);
    ls_hi += __shfl_xor_sync(0xffffffffu, ls_hi, 2);
    float inv_lo = 1.0f / ls_lo;
    float inv_hi = 1.0f / ls_hi;

    int r = lane >> 2, c2 = (lane & 3) * 2;
    __nv_bfloat16* op = g_oh + ((size_t)b*NN + q0 + qw)*II;
    #pragma unroll
    for (int t = 0; t < 16; t++) {
        __nv_bfloat162 h0 = __floats2bfloat162_rn(O[t][0]*inv_lo, O[t][1]*inv_lo);
        __nv_bfloat162 h1 = __floats2bfloat162_rn(O[t][2]*inv_hi, O[t][3]*inv_hi);
        *(uint32_t*)&op[(size_t)r*II + t*8 + c2]     = *(uint32_t*)&h0;
        *(uint32_t*)&op[(size_t)(r+8)*II + t*8 + c2] = *(uint32_t*)&h1;
    }
}

// ---------------- out projection (bf16 HMMA) + BN partial stats ----------------
extern __shared__ int4 smo4[];

__global__ __launch_bounds__(256) void k_oproj(const float* __restrict__ w2) {
    int4* sW = smo4;          // 128 c-rows x 16 units (32KB)
    int4* sO = smo4 + 2048;   // 64 n-rows x 16 units (16KB)

    int b  = blockIdx.z;
    int c0 = blockIdx.y * 128;
    int n0 = blockIdx.x * 64;
    int tid = threadIdx.x;
    int lane = tid & 31, warp = tid >> 5;

    #pragma unroll
    for (int p = 0; p < 8; p++) {
        int idx = tid + p*256;
        int row = idx >> 4, u = idx & 15;
        const float* wp = w2 + (size_t)(c0 + row)*II + u*8;
        float4 a = *(const float4*)wp;
        float4 bv = *(const float4*)(wp + 4);
        sW[row*16 + (u ^ (row & 7))] = pack8_bf16(a, bv, 1.0f);
    }
    #pragma unroll
    for (int p = 0; p < 4; p++) {
        int idx = tid + p*256;
        int row = idx >> 4, u = idx & 15;
        sO[row*16 + (u ^ (row & 7))] =
            ((const int4*)(g_oh + ((size_t)b*NN + n0 + row)*II))[u];
    }
    __syncthreads();

    uint32_t aW[8][4];
    int rowA = 16*warp + (lane & 15);
    int usel = (lane >> 4) & 1;
    #pragma unroll
    for (int kc = 0; kc < 8; kc++) {
        int u = 2*kc + usel;
        ldsm_x4(aW[kc], smem_u32(sW) + (uint32_t)((rowA*16 + (u ^ (rowA & 7))) * 16));
    }

    float s[8][4];
    #pragma unroll
    for (int j = 0; j < 8; j++) { s[j][0]=0.f; s[j][1]=0.f; s[j][2]=0.f; s[j][3]=0.f; }

    int rowB = (lane & 7) + ((lane >> 4) & 1) * 8;
    int uBsel = (lane >> 3) & 1;
    #pragma unroll
    for (int jp = 0; jp < 4; jp++) {
        int row = 16*jp + rowB;
        int sw = row & 7;
        #pragma unroll
        for (int kc = 0; kc < 8; kc++) {
            int u = 2*kc + uBsel;
            uint32_t bO[4];
            ldsm_x4(bO, smem_u32(sO) + (uint32_t)((row*16 + (u ^ sw)) * 16));
            mma16816(s[2*jp],   aW[kc], bO[0], bO[1]);
            mma16816(s[2*jp+1], aW[kc], bO[2], bO[3]);
        }
    }

    int r = lane >> 2, cn = (lane & 3) * 2;
    int crow = c0 + 16*warp + r;
    float ps0=0.f, pq0=0.f, ps1=0.f, pq1=0.f;
    #pragma unroll
    for (int j = 0; j < 8; j++) {
        *(float2*)&g_out[((size_t)(b*CC + crow))*NN + n0 + 8*j + cn]     = make_float2(s[j][0], s[j][1]);
        *(float2*)&g_out[((size_t)(b*CC + crow + 8))*NN + n0 + 8*j + cn] = make_float2(s[j][2], s[j][3]);
        ps0 += s[j][0] + s[j][1];
        pq0 += s[j][0]*s[j][0] + s[j][1]*s[j][1];
        ps1 += s[j][2] + s[j][3];
        pq1 += s[j][2]*s[j][2] + s[j][3]*s[j][3];
    }
    ps0 += __shfl_xor_sync(0xffffffffu, ps0, 1);
    ps0 += __shfl_xor_sync(0xffffffffu, ps0, 2);
    pq0 += __shfl_xor_sync(0xffffffffu, pq0, 1);
    pq0 += __shfl_xor_sync(0xffffffffu, pq0, 2);
    ps1 += __shfl_xor_sync(0xffffffffu, ps1, 1);
    ps1 += __shfl_xor_sync(0xffffffffu, ps1, 2);
    pq1 += __shfl_xor_sync(0xffffffffu, pq1, 1);
    pq1 += __shfl_xor_sync(0xffffffffu, pq1, 2);
    if ((lane & 3) == 0) {
        atomicAdd(&g_sum[crow], ps0);
        atomicAdd(&g_sumsq[crow], pq0);
        atomicAdd(&g_sum[crow + 8], ps1);
        atomicAdd(&g_sumsq[crow + 8], pq1);
    }
}

// ---------------- SE FC layers + BN finalize ----------------------------------
__global__ void k_se(const float* __restrict__ fc1w, const float* __restrict__ fc1b,
                     const float* __restrict__ fc2w, const float* __restrict__ fc2b,
                     const float* __restrict__ gamma, const float* __restrict__ beta) {
    __shared__ float spool[BB*CC];
    __shared__ float sh[BB*64];
    int tid = threadIdx.x;
    #pragma unroll
    for (int it = 0; it < 8; it++) spool[tid + it*256] = g_pool[tid + it*256] * (1.0f/NN);
    __syncthreads();
    #pragma unroll
    for (int pass = 0; pass < 2; pass++) {
        int t2 = tid + pass*256;
        int b = t2 >> 6, j = t2 & 63;
        float d = fc1b[j];
        #pragma unroll 8
        for (int c = 0; c < 256; c++) d += spool[b*256 + c] * fc1w[j*256 + c];
        sh[b*64 + j] = fmaxf(d, 0.f);
    }
    __syncthreads();
    #pragma unroll
    for (int it = 0; it < 8; it++) {
        int t2 = tid + it*256;
        int b = t2 >> 8, c = t2 & 255;
        float d = fc2b[c];
        #pragma unroll 8
        for (int j = 0; j < 64; j++) d += sh[b*64 + j] * fc2w[c*64 + j];
        g_chw[t2] = 1.f / (1.f + __expf(-d));
    }
    if (tid < 256) {
        float m  = g_sum[tid]   * (1.f/32768.f);
        float vr = g_sumsq[tid] * (1.f/32768.f) - m*m;
        float sc = gamma[tid] * rsqrtf(vr + 1e-5f);
        g_bns[tid] = sc;
        g_bnb[tid] = beta[tid] - m*sc;
    }
}

// ---------------- finalize ----------------------------------------------------
__global__ void k_final(const float* __restrict__ x, float* __restrict__ out) {
    size_t i4 = (size_t)blockIdx.x*256 + threadIdx.x;
    int bc = (int)(i4 >> 10);
    int c  = bc & 255;
    float4 xv = ((const float4*)x)[i4];
    float4 ov = ((const float4*)g_out)[i4];
    float sc = g_bns[c], bb = g_bnb[c], cw = g_chw[bc];
    float4 r;
    r.x = xv.x + (ov.x*sc + bb)*cw;
    r.y = xv.y + (ov.y*sc + bb)*cw;
    r.z = xv.z + (ov.z*sc + bb)*cw;
    r.w = xv.w + (ov.w*sc + bb)*cw;
    ((float4*)out)[i4] = r;
}

// ------------------------------------------------------------------------------
extern "C" void kernel_launch(void* const* d_in, const int* in_sizes, int n_in,
                              void* d_out, int out_size) {
    const float* x     = (const float*)d_in[0];
    const float* tw    = (const float*)d_in[1];
    const float* pw    = (const float*)d_in[2];
    const float* gw    = (const float*)d_in[3];
    const float* ow    = (const float*)d_in[4];
    const float* gamma = (const float*)d_in[5];
    const float* beta  = (const float*)d_in[6];
    const float* fc1w  = (const float*)d_in[7];
    const float* fc1b  = (const float*)d_in[8];
    const float* fc2w  = (const float*)d_in[9];
    const float* fc2b  = (const float*)d_in[10];
    float* out = (float*)d_out;

    cudaFuncSetAttribute(k_proj,  cudaFuncAttributeMaxDynamicSharedMemorySize, 65536);
    cudaFuncSetAttribute(k_flash, cudaFuncAttributeMaxDynamicSharedMemorySize, 49152);
    cudaFuncSetAttribute(k_oproj, cudaFuncAttributeMaxDynamicSharedMemorySize, 49152);

    k_zero<<<1, 256>>>();
    k_prew<<<48, 256>>>(tw, pw, gw);
    k_proj<<<dim3(64, 1, BB), 256, 65536>>>(x);
    k_flash<<<dim3(64, BB), 128, 49152>>>();
    k_oproj<<<dim3(64, 2, BB), 256, 49152>>>(ow);
    k_se<<<1, 256>>>(fc1w, fc1b, fc2w, fc2b, gamma, beta);
    k_final<<<8192, 256>>>(x, out);
}

// round 13
// speedup vs baseline: 1.0525x; 1.0525x over previous
#include <cuda_runtime.h>
#include <cuda_bf16.h>
#include <stdint.h>
#include <math.h>

#define BB 8
#define CC 256
#define NN 4096
#define II 128
#define LOG2E 1.4426950408889634f
#define QK_SCALE 0.08838834764831845f   // 1/sqrt(128)

// ---------------- scratch (device globals: allocation-free contract) ----------
static __device__ __nv_bfloat16 g_wh[3*II*CC];           // bf16 weights [m][i][c]
static __device__ __nv_bfloat16 g_qh[(size_t)BB*NN*II];  // theta, pre-scaled by QK_SCALE*LOG2E
static __device__ __nv_bfloat16 g_kh[(size_t)BB*NN*II];  // phi
static __device__ __nv_bfloat16 g_vh[(size_t)BB*NN*II];  // g
static __device__ __nv_bfloat16 g_oh[(size_t)BB*NN*II];  // normalized attn out, bf16 [B,N,I]
static __device__ float g_out[(size_t)BB*CC*NN];         // projected [B,C,N]
static __device__ float g_sum[CC];
static __device__ float g_sumsq[CC];
static __device__ float g_pool[BB*CC];                   // raw channel sums of x
static __device__ float g_chw[BB*CC];
static __device__ float g_bns[CC];
static __device__ float g_bnb[CC];

// ---------------- PTX helpers -------------------------------------------------
__device__ __forceinline__ uint32_t smem_u32(const void* p) {
    return (uint32_t)__cvta_generic_to_shared(p);
}
__device__ __forceinline__ void ldsm_x4(uint32_t* r, uint32_t addr) {
    asm volatile("ldmatrix.sync.aligned.m8n8.x4.shared.b16 {%0,%1,%2,%3},[%4];"
                 : "=r"(r[0]), "=r"(r[1]), "=r"(r[2]), "=r"(r[3]) : "r"(addr));
}
__device__ __forceinline__ void ldsm_x4_t(uint32_t* r, uint32_t addr) {
    asm volatile("ldmatrix.sync.aligned.m8n8.x4.trans.shared.b16 {%0,%1,%2,%3},[%4];"
                 : "=r"(r[0]), "=r"(r[1]), "=r"(r[2]), "=r"(r[3]) : "r"(addr));
}
__device__ __forceinline__ void mma16816(float* d, const uint32_t* a, uint32_t b0, uint32_t b1) {
    asm volatile("mma.sync.aligned.m16n8k16.row.col.f32.bf16.bf16.f32 "
                 "{%0,%1,%2,%3},{%4,%5,%6,%7},{%8,%9},{%0,%1,%2,%3};"
                 : "+f"(d[0]), "+f"(d[1]), "+f"(d[2]), "+f"(d[3])
                 : "r"(a[0]), "r"(a[1]), "r"(a[2]), "r"(a[3]), "r"(b0), "r"(b1));
}
__device__ __forceinline__ float ex2(float x) {
    float y;
    asm("ex2.approx.f32 %0, %1;" : "=f"(y) : "f"(x));
    return y;
}
__device__ __forceinline__ void cp_async16(uint32_t saddr, const void* gaddr) {
    asm volatile("cp.async.cg.shared.global [%0], [%1], 16;" :: "r"(saddr), "l"(gaddr));
}
#define CP_COMMIT()  asm volatile("cp.async.commit_group;" ::: "memory")
#define CP_WAIT0()   asm volatile("cp.async.wait_group 0;" ::: "memory")

__device__ __forceinline__ int4 pack8_bf16(float4 a, float4 b, float sc) {
    __nv_bfloat162 h0 = __floats2bfloat162_rn(a.x*sc, a.y*sc);
    __nv_bfloat162 h1 = __floats2bfloat162_rn(a.z*sc, a.w*sc);
    __nv_bfloat162 h2 = __floats2bfloat162_rn(b.x*sc, b.y*sc);
    __nv_bfloat162 h3 = __floats2bfloat162_rn(b.z*sc, b.w*sc);
    int4 pk;
    pk.x = *(int*)&h0; pk.y = *(int*)&h1; pk.z = *(int*)&h2; pk.w = *(int*)&h3;
    return pk;
}

// ---------------- zero accumulators -------------------------------------------
__global__ void k_zero() {
    int t = threadIdx.x;
    g_sum[t] = 0.f;
    g_sumsq[t] = 0.f;
    #pragma unroll
    for (int i = 0; i < 8; i++) g_pool[t + i*256] = 0.f;
}

// ---------------- weight pre-conversion to bf16 --------------------------------
__global__ void k_prew(const float* __restrict__ tw, const float* __restrict__ pw,
                       const float* __restrict__ gw) {
    int idx = blockIdx.x * 256 + threadIdx.x;   // 12288 threads x 8 elems
    int m = idx / 4096;
    int e = (idx % 4096) * 8;
    const float* w = (m == 0) ? tw : (m == 1 ? pw : gw);
    float4 a = *(const float4*)&w[e];
    float4 b = *(const float4*)&w[e + 4];
    *(int4*)&g_wh[m*II*CC + e] = pack8_bf16(a, b, 1.0f);
}

// ---------------- fused projections + SE pooling -------------------------------
extern __shared__ int4 smp4[];

__global__ __launch_bounds__(256) void k_proj(const float* __restrict__ x) {
    int4* sX4 = smp4;                 // 4 chunks x (64 rows x 8 units)
    int4* sW4 = smp4 + 2048;          // 2 bufs x 1024 int4
    __nv_bfloat16* sT = (__nv_bfloat16*)(smp4 + 2048);  // aliases sW (dead after cc loop)

    int b  = blockIdx.z;
    int n0 = blockIdx.x * 64;
    int tid = threadIdx.x;
    int lane = tid & 31, warp = tid >> 5;

    #pragma unroll
    for (int p = 0; p < 8; p++) {
        int idx = tid + p*256;
        int cc  = idx >> 9;
        int wi  = idx & 511;
        int row = wi >> 3, u = wi & 7;
        const float* xp = x + ((size_t)b*CC + cc*64 + row)*NN + n0 + u*8;
        float4 a = *(const float4*)xp;
        float4 bv = *(const float4*)(xp + 4);
        sX4[cc*512 + row*8 + (u ^ (row & 7))] = pack8_bf16(a, bv, 1.0f);
        float ss = (a.x + a.y) + (a.z + a.w) + (bv.x + bv.y) + (bv.z + bv.w);
        ss += __shfl_xor_sync(0xffffffffu, ss, 1);
        ss += __shfl_xor_sync(0xffffffffu, ss, 2);
        ss += __shfl_xor_sync(0xffffffffu, ss, 4);
        if ((lane & 7) == 0) atomicAdd(&g_pool[b*CC + cc*64 + row], ss);
    }

    int rowA = 16*warp + (lane & 15);
    int rbase = lane & 15;
    int usel = (lane >> 4) & 1;
    int ir = 16*warp + (lane >> 2);
    int cb = (lane & 3) * 2;

    #pragma unroll 1
    for (int m = 0; m < 3; m++) {
        __nv_bfloat16* outp = (m == 0) ? g_qh : (m == 1 ? g_kh : g_vh);
        float qs = (m == 0) ? (QK_SCALE * LOG2E) : 1.0f;
        const __nv_bfloat16* wm = g_wh + m*II*CC;

        float acc[8][4];
        #pragma unroll
        for (int t = 0; t < 8; t++) { acc[t][0]=0.f; acc[t][1]=0.f; acc[t][2]=0.f; acc[t][3]=0.f; }

        #pragma unroll 1
        for (int cc = 0; cc < 4; cc++) {
            int buf = cc & 1;
            #pragma unroll
            for (int p = 0; p < 4; p++) {
                int idx = tid + p*256;
                int row = idx >> 3, u = idx & 7;
                sW4[buf*1024 + row*8 + (u ^ (row & 7))] =
                    *(const int4*)&wm[(size_t)row*CC + cc*64 + u*8];
            }
            __syncthreads();

            uint32_t aW[4][4];
            #pragma unroll
            for (int kc = 0; kc < 4; kc++) {
                int u = 2*kc + usel;
                ldsm_x4(aW[kc], smem_u32(sW4) +
                        (uint32_t)((buf*1024 + rowA*8 + (u ^ (rowA & 7))) * 16));
            }
            #pragma unroll
            for (int kc = 0; kc < 4; kc++) {
                int row = 16*kc + rbase;
                int sw = row & 7;
                #pragma unroll
                for (int nb = 0; nb < 4; nb++) {
                    int u = 2*nb + usel;
                    uint32_t bX[4];
                    ldsm_x4_t(bX, smem_u32(sX4) + (uint32_t)((cc*512 + row*8 + (u ^ sw)) * 16));
                    mma16816(acc[2*nb],   aW[kc], bX[0], bX[1]);
                    mma16816(acc[2*nb+1], aW[kc], bX[2], bX[3]);
                }
            }
        }

        __syncthreads();
        #pragma unroll
        for (int nb = 0; nb < 4; nb++) {
            #pragma unroll
            for (int h = 0; h < 2; h++) {
                int a = 2*nb + h;
                int nn = 16*nb + 8*h + cb;
                sT[nn*136 + ir]         = __float2bfloat16(acc[a][0]*qs);
                sT[(nn+1)*136 + ir]     = __float2bfloat16(acc[a][1]*qs);
                sT[nn*136 + ir + 8]     = __float2bfloat16(acc[a][2]*qs);
                sT[(nn+1)*136 + ir + 8] = __float2bfloat16(acc[a][3]*qs);
            }
        }
        __syncthreads();
        #pragma unroll
        for (int p = 0; p < 4; p++) {
            int idx = tid + p*256;
            int nn = idx >> 4, u = idx & 15;
            *(int4*)&outp[((size_t)b*NN + n0 + nn)*II + u*8] = *(int4*)&sT[nn*136 + u*8];
        }
        __syncthreads();
    }
}

// ---------------- flash attention: bf16 HMMA, no-max softmax ------------------
// R11 structure (64q/CTA, BN=64, m16 warps, staging at loop top).
// S-loop reordered kc-outer/jp-inner: accumulator reuse distance 2 -> 8,
// hiding HMMA latency inside each warp. Numerics bit-identical (same per-
// element accumulation order over kc).
extern __shared__ __nv_bfloat16 smh[];

__global__ __launch_bounds__(128, 2) void k_flash() {
    int4* sQ4 = (int4*)smh;
    int4* sK4 = (int4*)(smh + 64*128);       // 2 bufs x 1024 int4
    int4* sV4 = (int4*)(smh + 3*64*128);     // 2 bufs x 1024 int4

    int b  = blockIdx.y;
    int q0 = blockIdx.x * 64;
    int tid = threadIdx.x;
    int lane = tid & 31, warp = tid >> 5;
    int qw = warp * 16;

    const __nv_bfloat16* kp = g_kh + (size_t)b*NN*II;
    const __nv_bfloat16* vp = g_vh + (size_t)b*NN*II;

    auto stage = [&](int buf, int kt) {
        const int4* kg = (const int4*)(kp + (size_t)(kt*64)*II);
        const int4* vg = (const int4*)(vp + (size_t)(kt*64)*II);
        uint32_t kb = smem_u32(sK4 + buf*1024);
        uint32_t vb = smem_u32(sV4 + buf*1024);
        #pragma unroll
        for (int p = 0; p < 8; p++) {
            int idx = tid + p*128;
            int row = idx >> 4, u = idx & 15;
            uint32_t d = (uint32_t)((row*16 + (u ^ (row & 7))) * 16);
            cp_async16(kb + d, kg + row*16 + u);
            cp_async16(vb + d, vg + row*16 + u);
        }
    };

    stage(0, 0);
    CP_COMMIT();

    {
        const int4* qg = (const int4*)(g_qh + ((size_t)b*NN + q0)*II);
        #pragma unroll
        for (int p = 0; p < 8; p++) {
            int idx = tid + p*128;
            int row = idx >> 4, u = idx & 15;
            sQ4[row*16 + (u ^ (row & 7))] = qg[row*16 + u];
        }
    }
    __syncthreads();

    uint32_t aQ[8][4];
    {
        int row = qw + (lane & 15);
        #pragma unroll
        for (int kc = 0; kc < 8; kc++) {
            int u = 2*kc + ((lane >> 4) & 1);
            uint32_t addr = smem_u32(sQ4) + (uint32_t)((row*16 + (u ^ (row & 7))) * 16);
            ldsm_x4(aQ[kc], addr);
        }
    }

    float O[16][4];
    #pragma unroll
    for (int t = 0; t < 16; t++) { O[t][0]=0.f; O[t][1]=0.f; O[t][2]=0.f; O[t][3]=0.f; }
    float ls_lo = 0.f, ls_hi = 0.f;

    int rowB = (lane & 7) + ((lane >> 4) & 1) * 8;
    int uBsel = (lane >> 3) & 1;
    int rowV = (lane & 15);
    int uVsel = (lane >> 4) & 1;

    for (int kt = 0; kt < 64; kt++) {
        int cur = kt & 1;
        CP_WAIT0();
        __syncthreads();

        if (kt < 63) {
            stage(cur ^ 1, kt + 1);
            CP_COMMIT();
        }

        uint32_t sKb = smem_u32(sK4 + cur*1024);
        uint32_t sVb = smem_u32(sV4 + cur*1024);

        // ---- S = Q K^T: kc-outer, 8 independent accumulators in flight ----
        float S[8][4];
        #pragma unroll
        for (int j = 0; j < 8; j++) { S[j][0]=0.f; S[j][1]=0.f; S[j][2]=0.f; S[j][3]=0.f; }

        #pragma unroll
        for (int kc = 0; kc < 8; kc++) {
            uint32_t bK[4][4];
            int u = 2*kc + uBsel;
            #pragma unroll
            for (int jp = 0; jp < 4; jp++) {
                int row = 16*jp + rowB;
                int sw = row & 7;
                ldsm_x4(bK[jp], sKb + (uint32_t)((row*16 + (u ^ sw)) * 16));
            }
            #pragma unroll
            for (int jp = 0; jp < 4; jp++) {
                mma16816(S[2*jp],   aQ[kc], bK[jp][0], bK[jp][1]);
                mma16816(S[2*jp+1], aQ[kc], bK[jp][2], bK[jp][3]);
            }
        }

        uint32_t aP[4][4];
        #pragma unroll
        for (int kc2 = 0; kc2 < 4; kc2++) {
            float p00 = ex2(S[2*kc2][0]),   p01 = ex2(S[2*kc2][1]);
            float p02 = ex2(S[2*kc2][2]),   p03 = ex2(S[2*kc2][3]);
            float p10 = ex2(S[2*kc2+1][0]), p11 = ex2(S[2*kc2+1][1]);
            float p12 = ex2(S[2*kc2+1][2]), p13 = ex2(S[2*kc2+1][3]);
            ls_lo += (p00 + p01) + (p10 + p11);
            ls_hi += (p02 + p03) + (p12 + p13);
            __nv_bfloat162 h0 = __floats2bfloat162_rn(p00, p01);
            __nv_bfloat162 h1 = __floats2bfloat162_rn(p02, p03);
            __nv_bfloat162 h2 = __floats2bfloat162_rn(p10, p11);
            __nv_bfloat162 h3 = __floats2bfloat162_rn(p12, p13);
            aP[kc2][0] = *(uint32_t*)&h0;
            aP[kc2][1] = *(uint32_t*)&h1;
            aP[kc2][2] = *(uint32_t*)&h2;
            aP[kc2][3] = *(uint32_t*)&h3;
        }

        #pragma unroll
        for (int kc2 = 0; kc2 < 4; kc2++) {
            int row = 16*kc2 + rowV;
            int sw = row & 7;
            #pragma unroll
            for (int nt2 = 0; nt2 < 8; nt2++) {
                int u = 2*nt2 + uVsel;
                uint32_t bV[4];
                ldsm_x4_t(bV, sVb + (uint32_t)((row*16 + (u ^ sw)) * 16));
                mma16816(O[2*nt2],   aP[kc2], bV[0], bV[1]);
                mma16816(O[2*nt2+1], aP[kc2], bV[2], bV[3]);
            }
        }
    }

    ls_lo += __shfl_xor_sync(0xffffffffu, ls_lo, 1);
    ls_lo += __shfl_xor_sync(0xffffffffu, ls_lo, 2);
    ls_hi += __shfl_xor_sync(0xffffffffu, ls_hi, 1);
    ls_hi += __shfl_xor_sync(0xffffffffu, ls_hi, 2);
    float inv_lo = 1.0f / ls_lo;
    float inv_hi = 1.0f / ls_hi;

    int r = lane >> 2, c2 = (lane & 3) * 2;
    __nv_bfloat16* op = g_oh + ((size_t)b*NN + q0 + qw)*II;
    #pragma unroll
    for (int t = 0; t < 16; t++) {
        __nv_bfloat162 h0 = __floats2bfloat162_rn(O[t][0]*inv_lo, O[t][1]*inv_lo);
        __nv_bfloat162 h1 = __floats2bfloat162_rn(O[t][2]*inv_hi, O[t][3]*inv_hi);
        *(uint32_t*)&op[(size_t)r*II + t*8 + c2]     = *(uint32_t*)&h0;
        *(uint32_t*)&op[(size_t)(r+8)*II + t*8 + c2] = *(uint32_t*)&h1;
    }
}

// ---------------- out projection (bf16 HMMA) + BN partial stats ----------------
extern __shared__ int4 smo4[];

__global__ __launch_bounds__(256) void k_oproj(const float* __restrict__ w2) {
    int4* sW = smo4;          // 128 c-rows x 16 units (32KB)
    int4* sO = smo4 + 2048;   // 64 n-rows x 16 units (16KB)

    int b  = blockIdx.z;
    int c0 = blockIdx.y * 128;
    int n0 = blockIdx.x * 64;
    int tid = threadIdx.x;
    int lane = tid & 31, warp = tid >> 5;

    #pragma unroll
    for (int p = 0; p < 8; p++) {
        int idx = tid + p*256;
        int row = idx >> 4, u = idx & 15;
        const float* wp = w2 + (size_t)(c0 + row)*II + u*8;
        float4 a = *(const float4*)wp;
        float4 bv = *(const float4*)(wp + 4);
        sW[row*16 + (u ^ (row & 7))] = pack8_bf16(a, bv, 1.0f);
    }
    #pragma unroll
    for (int p = 0; p < 4; p++) {
        int idx = tid + p*256;
        int row = idx >> 4, u = idx & 15;
        sO[row*16 + (u ^ (row & 7))] =
            ((const int4*)(g_oh + ((size_t)b*NN + n0 + row)*II))[u];
    }
    __syncthreads();

    uint32_t aW[8][4];
    int rowA = 16*warp + (lane & 15);
    int usel = (lane >> 4) & 1;
    #pragma unroll
    for (int kc = 0; kc < 8; kc++) {
        int u = 2*kc + usel;
        ldsm_x4(aW[kc], smem_u32(sW) + (uint32_t)((rowA*16 + (u ^ (rowA & 7))) * 16));
    }

    float s[8][4];
    #pragma unroll
    for (int j = 0; j < 8; j++) { s[j][0]=0.f; s[j][1]=0.f; s[j][2]=0.f; s[j][3]=0.f; }

    int rowB = (lane & 7) + ((lane >> 4) & 1) * 8;
    int uBsel = (lane >> 3) & 1;
    #pragma unroll
    for (int kc = 0; kc < 8; kc++) {
        uint32_t bO[4][4];
        int u = 2*kc + uBsel;
        #pragma unroll
        for (int jp = 0; jp < 4; jp++) {
            int row = 16*jp + rowB;
            int sw = row & 7;
            ldsm_x4(bO[jp], smem_u32(sO) + (uint32_t)((row*16 + (u ^ sw)) * 16));
        }
        #pragma unroll
        for (int jp = 0; jp < 4; jp++) {
            mma16816(s[2*jp],   aW[kc], bO[jp][0], bO[jp][1]);
            mma16816(s[2*jp+1], aW[kc], bO[jp][2], bO[jp][3]);
        }
    }

    int r = lane >> 2, cn = (lane & 3) * 2;
    int crow = c0 + 16*warp + r;
    float ps0=0.f, pq0=0.f, ps1=0.f, pq1=0.f;
    #pragma unroll
    for (int j = 0; j < 8; j++) {
        *(float2*)&g_out[((size_t)(b*CC + crow))*NN + n0 + 8*j + cn]     = make_float2(s[j][0], s[j][1]);
        *(float2*)&g_out[((size_t)(b*CC + crow + 8))*NN + n0 + 8*j + cn] = make_float2(s[j][2], s[j][3]);
        ps0 += s[j][0] + s[j][1];
        pq0 += s[j][0]*s[j][0] + s[j][1]*s[j][1];
        ps1 += s[j][2] + s[j][3];
        pq1 += s[j][2]*s[j][2] + s[j][3]*s[j][3];
    }
    ps0 += __shfl_xor_sync(0xffffffffu, ps0, 1);
    ps0 += __shfl_xor_sync(0xffffffffu, ps0, 2);
    pq0 += __shfl_xor_sync(0xffffffffu, pq0, 1);
    pq0 += __shfl_xor_sync(0xffffffffu, pq0, 2);
    ps1 += __shfl_xor_sync(0xffffffffu, ps1, 1);
    ps1 += __shfl_xor_sync(0xffffffffu, ps1, 2);
    pq1 += __shfl_xor_sync(0xffffffffu, pq1, 1);
    pq1 += __shfl_xor_sync(0xffffffffu, pq1, 2);
    if ((lane & 3) == 0) {
        atomicAdd(&g_sum[crow], ps0);
        atomicAdd(&g_sumsq[crow], pq0);
        atomicAdd(&g_sum[crow + 8], ps1);
        atomicAdd(&g_sumsq[crow + 8], pq1);
    }
}

// ---------------- SE FC layers + BN finalize ----------------------------------
__global__ void k_se(const float* __restrict__ fc1w, const float* __restrict__ fc1b,
                     const float* __restrict__ fc2w, const float* __restrict__ fc2b,
                     const float* __restrict__ gamma, const float* __restrict__ beta) {
    __shared__ float spool[BB*CC];
    __shared__ float sh[BB*64];
    int tid = threadIdx.x;
    #pragma unroll
    for (int it = 0; it < 8; it++) spool[tid + it*256] = g_pool[tid + it*256] * (1.0f/NN);
    __syncthreads();
    #pragma unroll
    for (int pass = 0; pass < 2; pass++) {
        int t2 = tid + pass*256;
        int b = t2 >> 6, j = t2 & 63;
        float d = fc1b[j];
        #pragma unroll 8
        for (int c = 0; c < 256; c++) d += spool[b*256 + c] * fc1w[j*256 + c];
        sh[b*64 + j] = fmaxf(d, 0.f);
    }
    __syncthreads();
    #pragma unroll
    for (int it = 0; it < 8; it++) {
        int t2 = tid + it*256;
        int b = t2 >> 8, c = t2 & 255;
        float d = fc2b[c];
        #pragma unroll 8
        for (int j = 0; j < 64; j++) d += sh[b*64 + j] * fc2w[c*64 + j];
        g_chw[t2] = 1.f / (1.f + __expf(-d));
    }
    if (tid < 256) {
        float m  = g_sum[tid]   * (1.f/32768.f);
        float vr = g_sumsq[tid] * (1.f/32768.f) - m*m;
        float sc = gamma[tid] * rsqrtf(vr + 1e-5f);
        g_bns[tid] = sc;
        g_bnb[tid] = beta[tid] - m*sc;
    }
}

// ---------------- finalize ----------------------------------------------------
__global__ void k_final(const float* __restrict__ x, float* __restrict__ out) {
    size_t i4 = (size_t)blockIdx.x*256 + threadIdx.x;
    int bc = (int)(i4 >> 10);
    int c  = bc & 255;
    float4 xv = ((const float4*)x)[i4];
    float4 ov = ((const float4*)g_out)[i4];
    float sc = g_bns[c], bb = g_bnb[c], cw = g_chw[bc];
    float4 r;
    r.x = xv.x + (ov.x*sc + bb)*cw;
    r.y = xv.y + (ov.y*sc + bb)*cw;
    r.z = xv.z + (ov.z*sc + bb)*cw;
    r.w = xv.w + (ov.w*sc + bb)*cw;
    ((float4*)out)[i4] = r;
}

// ------------------------------------------------------------------------------
extern "C" void kernel_launch(void* const* d_in, const int* in_sizes, int n_in,
                              void* d_out, int out_size) {
    const float* x     = (const float*)d_in[0];
    const float* tw    = (const float*)d_in[1];
    const float* pw    = (const float*)d_in[2];
    const float* gw    = (const float*)d_in[3];
    const float* ow    = (const float*)d_in[4];
    const float* gamma = (const float*)d_in[5];
    const float* beta  = (const float*)d_in[6];
    const float* fc1w  = (const float*)d_in[7];
    const float* fc1b  = (const float*)d_in[8];
    const float* fc2w  = (const float*)d_in[9];
    const float* fc2b  = (const float*)d_in[10];
    float* out = (float*)d_out;

    cudaFuncSetAttribute(k_proj,  cudaFuncAttributeMaxDynamicSharedMemorySize, 65536);
    cudaFuncSetAttribute(k_flash, cudaFuncAttributeMaxDynamicSharedMemorySize, 81920);
    cudaFuncSetAttribute(k_oproj, cudaFuncAttributeMaxDynamicSharedMemorySize, 49152);

    k_zero<<<1, 256>>>();
    k_prew<<<48, 256>>>(tw, pw, gw);
    k_proj<<<dim3(64, 1, BB), 256, 65536>>>(x);
    k_flash<<<dim3(64, BB), 128, 81920>>>();
    k_oproj<<<dim3(64, 2, BB), 256, 49152>>>(ow);
    k_se<<<1, 256>>>(fc1w, fc1b, fc2w, fc2b, gamma, beta);
    k_final<<<8192, 256>>>(x, out);
}

// round 15
// speedup vs baseline: 1.1040x; 1.0489x over previous
#include <cuda_runtime.h>
#include <cuda_bf16.h>
#include <stdint.h>
#include <math.h>

#define BB 8
#define CC 256
#define NN 4096
#define II 128
#define LOG2E 1.4426950408889634f
#define QK_SCALE 0.08838834764831845f   // 1/sqrt(128)

// ---------------- scratch (device globals: allocation-free contract) ----------
static __device__ __nv_bfloat16 g_wh[3*II*CC];           // bf16 weights [m][i][c]
static __device__ __nv_bfloat16 g_w2h[CC*II];            // bf16 out_w [c][i]
static __device__ __nv_bfloat16 g_qh[(size_t)BB*NN*II];  // theta, pre-scaled by QK_SCALE*LOG2E
static __device__ __nv_bfloat16 g_kh[(size_t)BB*NN*II];  // phi
static __device__ __nv_bfloat16 g_vh[(size_t)BB*NN*II];  // g
static __device__ float g_out[(size_t)BB*CC*NN];         // projected [B,C,N]
static __device__ float g_sum[CC];
static __device__ float g_sumsq[CC];
static __device__ float g_pool[BB*CC];                   // raw channel sums of x
static __device__ float g_chw[BB*CC];
static __device__ float g_bns[CC];
static __device__ float g_bnb[CC];

// ---------------- PTX helpers -------------------------------------------------
__device__ __forceinline__ uint32_t smem_u32(const void* p) {
    return (uint32_t)__cvta_generic_to_shared(p);
}
__device__ __forceinline__ void ldsm_x4(uint32_t* r, uint32_t addr) {
    asm volatile("ldmatrix.sync.aligned.m8n8.x4.shared.b16 {%0,%1,%2,%3},[%4];"
                 : "=r"(r[0]), "=r"(r[1]), "=r"(r[2]), "=r"(r[3]) : "r"(addr));
}
__device__ __forceinline__ void ldsm_x4_t(uint32_t* r, uint32_t addr) {
    asm volatile("ldmatrix.sync.aligned.m8n8.x4.trans.shared.b16 {%0,%1,%2,%3},[%4];"
                 : "=r"(r[0]), "=r"(r[1]), "=r"(r[2]), "=r"(r[3]) : "r"(addr));
}
__device__ __forceinline__ void mma16816(float* d, const uint32_t* a, uint32_t b0, uint32_t b1) {
    asm volatile("mma.sync.aligned.m16n8k16.row.col.f32.bf16.bf16.f32 "
                 "{%0,%1,%2,%3},{%4,%5,%6,%7},{%8,%9},{%0,%1,%2,%3};"
                 : "+f"(d[0]), "+f"(d[1]), "+f"(d[2]), "+f"(d[3])
                 : "r"(a[0]), "r"(a[1]), "r"(a[2]), "r"(a[3]), "r"(b0), "r"(b1));
}
__device__ __forceinline__ float ex2(float x) {
    float y;
    asm("ex2.approx.f32 %0, %1;" : "=f"(y) : "f"(x));
    return y;
}
__device__ __forceinline__ void cp_async16(uint32_t saddr, const void* gaddr) {
    asm volatile("cp.async.cg.shared.global [%0], [%1], 16;" :: "r"(saddr), "l"(gaddr));
}
#define CP_COMMIT()  asm volatile("cp.async.commit_group;" ::: "memory")
#define CP_WAIT0()   asm volatile("cp.async.wait_group 0;" ::: "memory")

__device__ __forceinline__ int4 pack8_bf16(float4 a, float4 b, float sc) {
    __nv_bfloat162 h0 = __floats2bfloat162_rn(a.x*sc, a.y*sc);
    __nv_bfloat162 h1 = __floats2bfloat162_rn(a.z*sc, a.w*sc);
    __nv_bfloat162 h2 = __floats2bfloat162_rn(b.x*sc, b.y*sc);
    __nv_bfloat162 h3 = __floats2bfloat162_rn(b.z*sc, b.w*sc);
    int4 pk;
    pk.x = *(int*)&h0; pk.y = *(int*)&h1; pk.z = *(int*)&h2; pk.w = *(int*)&h3;
    return pk;
}

// ---------------- zero accumulators -------------------------------------------
__global__ void k_zero() {
    int t = threadIdx.x;
    g_sum[t] = 0.f;
    g_sumsq[t] = 0.f;
    #pragma unroll
    for (int i = 0; i < 8; i++) g_pool[t + i*256] = 0.f;
}

// ---------------- weight pre-conversion to bf16 --------------------------------
// m 0..2 -> g_wh (theta/phi/g, [i][c]); m==3 -> g_w2h (out_w [c][i]).
// Each matrix = 32768 elems = 4096 threads x 8 -> 4 x 4096 = 64 blocks of 256.
__global__ void k_prew(const float* __restrict__ tw, const float* __restrict__ pw,
                       const float* __restrict__ gw, const float* __restrict__ ow) {
    int idx = blockIdx.x * 256 + threadIdx.x;   // 64 blocks = 16384 threads
    int m = idx >> 12;
    int e = (idx & 4095) * 8;
    const float* w = (m == 0) ? tw : (m == 1 ? pw : (m == 2 ? gw : ow));
    __nv_bfloat16* dst = (m < 3) ? (g_wh + m*II*CC) : g_w2h;
    float4 a = *(const float4*)&w[e];
    float4 b = *(const float4*)&w[e + 4];
    *(int4*)&dst[e] = pack8_bf16(a, b, 1.0f);
}

// ---------------- fused projections + SE pooling -------------------------------
extern __shared__ int4 smp4[];

__global__ __launch_bounds__(256) void k_proj(const float* __restrict__ x) {
    int4* sX4 = smp4;                 // 4 chunks x (64 rows x 8 units)
    int4* sW4 = smp4 + 2048;          // 2 bufs x 1024 int4
    __nv_bfloat16* sT = (__nv_bfloat16*)(smp4 + 2048);  // aliases sW (dead after cc loop)

    int b  = blockIdx.z;
    int n0 = blockIdx.x * 64;
    int tid = threadIdx.x;
    int lane = tid & 31, warp = tid >> 5;

    #pragma unroll
    for (int p = 0; p < 8; p++) {
        int idx = tid + p*256;
        int cc  = idx >> 9;
        int wi  = idx & 511;
        int row = wi >> 3, u = wi & 7;
        const float* xp = x + ((size_t)b*CC + cc*64 + row)*NN + n0 + u*8;
        float4 a = *(const float4*)xp;
        float4 bv = *(const float4*)(xp + 4);
        sX4[cc*512 + row*8 + (u ^ (row & 7))] = pack8_bf16(a, bv, 1.0f);
        float ss = (a.x + a.y) + (a.z + a.w) + (bv.x + bv.y) + (bv.z + bv.w);
        ss += __shfl_xor_sync(0xffffffffu, ss, 1);
        ss += __shfl_xor_sync(0xffffffffu, ss, 2);
        ss += __shfl_xor_sync(0xffffffffu, ss, 4);
        if ((lane & 7) == 0) atomicAdd(&g_pool[b*CC + cc*64 + row], ss);
    }

    int rowA = 16*warp + (lane & 15);
    int rbase = lane & 15;
    int usel = (lane >> 4) & 1;
    int ir = 16*warp + (lane >> 2);
    int cb = (lane & 3) * 2;

    #pragma unroll 1
    for (int m = 0; m < 3; m++) {
        __nv_bfloat16* outp = (m == 0) ? g_qh : (m == 1 ? g_kh : g_vh);
        float qs = (m == 0) ? (QK_SCALE * LOG2E) : 1.0f;
        const __nv_bfloat16* wm = g_wh + m*II*CC;

        float acc[8][4];
        #pragma unroll
        for (int t = 0; t < 8; t++) { acc[t][0]=0.f; acc[t][1]=0.f; acc[t][2]=0.f; acc[t][3]=0.f; }

        #pragma unroll 1
        for (int cc = 0; cc < 4; cc++) {
            int buf = cc & 1;
            #pragma unroll
            for (int p = 0; p < 4; p++) {
                int idx = tid + p*256;
                int row = idx >> 3, u = idx & 7;
                sW4[buf*1024 + row*8 + (u ^ (row & 7))] =
                    *(const int4*)&wm[(size_t)row*CC + cc*64 + u*8];
            }
            __syncthreads();

            uint32_t aW[4][4];
            #pragma unroll
            for (int kc = 0; kc < 4; kc++) {
                int u = 2*kc + usel;
                ldsm_x4(aW[kc], smem_u32(sW4) +
                        (uint32_t)((buf*1024 + rowA*8 + (u ^ (rowA & 7))) * 16));
            }
            #pragma unroll
            for (int kc = 0; kc < 4; kc++) {
                int row = 16*kc + rbase;
                int sw = row & 7;
                #pragma unroll
                for (int nb = 0; nb < 4; nb++) {
                    int u = 2*nb + usel;
                    uint32_t bX[4];
                    ldsm_x4_t(bX, smem_u32(sX4) + (uint32_t)((cc*512 + row*8 + (u ^ sw)) * 16));
                    mma16816(acc[2*nb],   aW[kc], bX[0], bX[1]);
                    mma16816(acc[2*nb+1], aW[kc], bX[2], bX[3]);
                }
            }
        }

        __syncthreads();
        #pragma unroll
        for (int nb = 0; nb < 4; nb++) {
            #pragma unroll
            for (int h = 0; h < 2; h++) {
                int a = 2*nb + h;
                int nn = 16*nb + 8*h + cb;
                sT[nn*136 + ir]         = __float2bfloat16(acc[a][0]*qs);
                sT[(nn+1)*136 + ir]     = __float2bfloat16(acc[a][1]*qs);
                sT[nn*136 + ir + 8]     = __float2bfloat16(acc[a][2]*qs);
                sT[(nn+1)*136 + ir + 8] = __float2bfloat16(acc[a][3]*qs);
            }
        }
        __syncthreads();
        #pragma unroll
        for (int p = 0; p < 4; p++) {
            int idx = tid + p*256;
            int nn = idx >> 4, u = idx & 15;
            *(int4*)&outp[((size_t)b*NN + n0 + nn)*II + u*8] = *(int4*)&sT[nn*136 + u*8];
        }
        __syncthreads();
    }
}

// ---------------- flash attention + fused out-projection ----------------------
// Mainloop: R11 exactly. Epilogue: normalized O (bf16) written into the dead sK
// smem region (oproj staging layout); w2 staged in 64-row chunks into the dead
// sV region; k_oproj's MMA + g_out stores + BN partials run in-CTA.
extern __shared__ __nv_bfloat16 smh[];

__global__ __launch_bounds__(128, 2) void k_flash() {
    int4* sQ4 = (int4*)smh;
    int4* sK4 = (int4*)(smh + 64*128);       // 2 bufs x 1024 int4
    int4* sV4 = (int4*)(smh + 3*64*128);     // 2 bufs x 1024 int4

    int b  = blockIdx.y;
    int q0 = blockIdx.x * 64;
    int tid = threadIdx.x;
    int lane = tid & 31, warp = tid >> 5;
    int qw = warp * 16;

    const __nv_bfloat16* kp = g_kh + (size_t)b*NN*II;
    const __nv_bfloat16* vp = g_vh + (size_t)b*NN*II;

    auto stage = [&](int buf, int kt) {
        const int4* kg = (const int4*)(kp + (size_t)(kt*64)*II);
        const int4* vg = (const int4*)(vp + (size_t)(kt*64)*II);
        uint32_t kb = smem_u32(sK4 + buf*1024);
        uint32_t vb = smem_u32(sV4 + buf*1024);
        #pragma unroll
        for (int p = 0; p < 8; p++) {
            int idx = tid + p*128;
            int row = idx >> 4, u = idx & 15;
            uint32_t d = (uint32_t)((row*16 + (u ^ (row & 7))) * 16);
            cp_async16(kb + d, kg + row*16 + u);
            cp_async16(vb + d, vg + row*16 + u);
        }
    };

    stage(0, 0);
    CP_COMMIT();

    {
        const int4* qg = (const int4*)(g_qh + ((size_t)b*NN + q0)*II);
        #pragma unroll
        for (int p = 0; p < 8; p++) {
            int idx = tid + p*128;
            int row = idx >> 4, u = idx & 15;
            sQ4[row*16 + (u ^ (row & 7))] = qg[row*16 + u];
        }
    }
    __syncthreads();

    uint32_t aQ[8][4];
    {
        int row = qw + (lane & 15);
        #pragma unroll
        for (int kc = 0; kc < 8; kc++) {
            int u = 2*kc + ((lane >> 4) & 1);
            uint32_t addr = smem_u32(sQ4) + (uint32_t)((row*16 + (u ^ (row & 7))) * 16);
            ldsm_x4(aQ[kc], addr);
        }
    }

    float O[16][4];
    #pragma unroll
    for (int t = 0; t < 16; t++) { O[t][0]=0.f; O[t][1]=0.f; O[t][2]=0.f; O[t][3]=0.f; }
    float ls_lo = 0.f, ls_hi = 0.f;

    int rowB = (lane & 7) + ((lane >> 4) & 1) * 8;
    int uBsel = (lane >> 3) & 1;
    int rowV = (lane & 15);
    int uVsel = (lane >> 4) & 1;

    for (int kt = 0; kt < 64; kt++) {
        int cur = kt & 1;
        CP_WAIT0();
        __syncthreads();

        if (kt < 63) {
            stage(cur ^ 1, kt + 1);
            CP_COMMIT();
        }

        uint32_t sKb = smem_u32(sK4 + cur*1024);
        uint32_t sVb = smem_u32(sV4 + cur*1024);

        float S[8][4];
        #pragma unroll
        for (int j = 0; j < 8; j++) { S[j][0]=0.f; S[j][1]=0.f; S[j][2]=0.f; S[j][3]=0.f; }

        #pragma unroll
        for (int jp = 0; jp < 4; jp++) {
            int row = 16*jp + rowB;
            int sw = row & 7;
            #pragma unroll
            for (int kc = 0; kc < 8; kc++) {
                int u = 2*kc + uBsel;
                uint32_t bK[4];
                ldsm_x4(bK, sKb + (uint32_t)((row*16 + (u ^ sw)) * 16));
                mma16816(S[2*jp],   aQ[kc], bK[0], bK[1]);
                mma16816(S[2*jp+1], aQ[kc], bK[2], bK[3]);
            }
        }

        uint32_t aP[4][4];
        #pragma unroll
        for (int kc2 = 0; kc2 < 4; kc2++) {
            float p00 = ex2(S[2*kc2][0]),   p01 = ex2(S[2*kc2][1]);
            float p02 = ex2(S[2*kc2][2]),   p03 = ex2(S[2*kc2][3]);
            float p10 = ex2(S[2*kc2+1][0]), p11 = ex2(S[2*kc2+1][1]);
            float p12 = ex2(S[2*kc2+1][2]), p13 = ex2(S[2*kc2+1][3]);
            ls_lo += (p00 + p01) + (p10 + p11);
            ls_hi += (p02 + p03) + (p12 + p13);
            __nv_bfloat162 h0 = __floats2bfloat162_rn(p00, p01);
            __nv_bfloat162 h1 = __floats2bfloat162_rn(p02, p03);
            __nv_bfloat162 h2 = __floats2bfloat162_rn(p10, p11);
            __nv_bfloat162 h3 = __floats2bfloat162_rn(p12, p13);
            aP[kc2][0] = *(uint32_t*)&h0;
            aP[kc2][1] = *(uint32_t*)&h1;
            aP[kc2][2] = *(uint32_t*)&h2;
            aP[kc2][3] = *(uint32_t*)&h3;
        }

        #pragma unroll
        for (int kc2 = 0; kc2 < 4; kc2++) {
            int row = 16*kc2 + rowV;
            int sw = row & 7;
            #pragma unroll
            for (int nt2 = 0; nt2 < 8; nt2++) {
                int u = 2*nt2 + uVsel;
                uint32_t bV[4];
                ldsm_x4_t(bV, sVb + (uint32_t)((row*16 + (u ^ sw)) * 16));
                mma16816(O[2*nt2],   aP[kc2], bV[0], bV[1]);
                mma16816(O[2*nt2+1], aP[kc2], bV[2], bV[3]);
            }
        }
    }

    ls_lo += __shfl_xor_sync(0xffffffffu, ls_lo, 1);
    ls_lo += __shfl_xor_sync(0xffffffffu, ls_lo, 2);
    ls_hi += __shfl_xor_sync(0xffffffffu, ls_hi, 1);
    ls_hi += __shfl_xor_sync(0xffffffffu, ls_hi, 2);
    float inv_lo = 1.0f / ls_lo;
    float inv_hi = 1.0f / ls_hi;

    // ================= fused out-projection epilogue =================
    __syncthreads();   // all warps finished mainloop smem reads

    char* sOe = (char*)smh + 16384;   // sK region: 64 n-rows x 256B, swizzled
    int rr = lane >> 2, cn = (lane & 3) * 2;
    #pragma unroll
    for (int t = 0; t < 16; t++) {
        __nv_bfloat162 h0 = __floats2bfloat162_rn(O[t][0]*inv_lo, O[t][1]*inv_lo);
        __nv_bfloat162 h1 = __floats2bfloat162_rn(O[t][2]*inv_hi, O[t][3]*inv_hi);
        int row0 = qw + rr, row1 = qw + 8 + rr;
        *(uint32_t*)(sOe + row0*256 + (t ^ (row0 & 7))*16 + cn*2) = *(uint32_t*)&h0;
        *(uint32_t*)(sOe + row1*256 + (t ^ (row1 & 7))*16 + cn*2) = *(uint32_t*)&h1;
    }

    int4* sVw = (int4*)((char*)smh + 49152);   // sV region: 64 c-rows x 16 units
    uint32_t sOeu = smem_u32(sOe);
    uint32_t sVwu = smem_u32(sVw);
    int rowA = 16*warp + (lane & 15);

    #pragma unroll 1
    for (int ch = 0; ch < 4; ch++) {
        __syncthreads();   // prev chunk's reads done (and sOe writes for ch=0)
        #pragma unroll
        for (int p = 0; p < 8; p++) {
            int idx = tid + p*128;
            int row = idx >> 4, u = idx & 15;
            sVw[row*16 + (u ^ (row & 7))] =
                *(const int4*)&g_w2h[(size_t)(ch*64 + row)*II + u*8];
        }
        __syncthreads();

        uint32_t aW[8][4];
        #pragma unroll
        for (int kc = 0; kc < 8; kc++) {
            int u = 2*kc + uVsel;
            ldsm_x4(aW[kc], sVwu + (uint32_t)((rowA*16 + (u ^ (rowA & 7))) * 16));
        }

        float s[8][4];
        #pragma unroll
        for (int j = 0; j < 8; j++) { s[j][0]=0.f; s[j][1]=0.f; s[j][2]=0.f; s[j][3]=0.f; }

        #pragma unroll
        for (int jp = 0; jp < 4; jp++) {
            int row = 16*jp + rowB;
            int sw = row & 7;
            #pragma unroll
            for (int kc = 0; kc < 8; kc++) {
                int u = 2*kc + uBsel;
                uint32_t bO[4];
                ldsm_x4(bO, sOeu + (uint32_t)((row*16 + (u ^ sw)) * 16));
                mma16816(s[2*jp],   aW[kc], bO[0], bO[1]);
                mma16816(s[2*jp+1], aW[kc], bO[2], bO[3]);
            }
        }

        int crow = ch*64 + 16*warp + rr;
        float ps0=0.f, pq0=0.f, ps1=0.f, pq1=0.f;
        #pragma unroll
        for (int j = 0; j < 8; j++) {
            *(float2*)&g_out[((size_t)(b*CC + crow))*NN + q0 + 8*j + cn]     = make_float2(s[j][0], s[j][1]);
            *(float2*)&g_out[((size_t)(b*CC + crow + 8))*NN + q0 + 8*j + cn] = make_float2(s[j][2], s[j][3]);
            ps0 += s[j][0] + s[j][1];
            pq0 += s[j][0]*s[j][0] + s[j][1]*s[j][1];
            ps1 += s[j][2] + s[j][3];
            pq1 += s[j][2]*s[j][2] + s[j][3]*s[j][3];
        }
        ps0 += __shfl_xor_sync(0xffffffffu, ps0, 1);
        ps0 += __shfl_xor_sync(0xffffffffu, ps0, 2);
        pq0 += __shfl_xor_sync(0xffffffffu, pq0, 1);
        pq0 += __shfl_xor_sync(0xffffffffu, pq0, 2);
        ps1 += __shfl_xor_sync(0xffffffffu, ps1, 1);
        ps1 += __shfl_xor_sync(0xffffffffu, ps1, 2);
        pq1 += __shfl_xor_sync(0xffffffffu, pq1, 1);
        pq1 += __shfl_xor_sync(0xffffffffu, pq1, 2);
        if ((lane & 3) == 0) {
            atomicAdd(&g_sum[crow], ps0);
            atomicAdd(&g_sumsq[crow], pq0);
            atomicAdd(&g_sum[crow + 8], ps1);
            atomicAdd(&g_sumsq[crow + 8], pq1);
        }
    }
}

// ---------------- SE FC layers + BN finalize ----------------------------------
__global__ void k_se(const float* __restrict__ fc1w, const float* __restrict__ fc1b,
                     const float* __restrict__ fc2w, const float* __restrict__ fc2b,
                     const float* __restrict__ gamma, const float* __restrict__ beta) {
    __shared__ float spool[BB*CC];
    __shared__ float sh[BB*64];
    int tid = threadIdx.x;
    #pragma unroll
    for (int it = 0; it < 8; it++) spool[tid + it*256] = g_pool[tid + it*256] * (1.0f/NN);
    __syncthreads();
    #pragma unroll
    for (int pass = 0; pass < 2; pass++) {
        int t2 = tid + pass*256;
        int b = t2 >> 6, j = t2 & 63;
        float d = fc1b[j];
        #pragma unroll 8
        for (int c = 0; c < 256; c++) d += spool[b*256 + c] * fc1w[j*256 + c];
        sh[b*64 + j] = fmaxf(d, 0.f);
    }
    __syncthreads();
    #pragma unroll
    for (int it = 0; it < 8; it++) {
        int t2 = tid + it*256;
        int b = t2 >> 8, c = t2 & 255;
        float d = fc2b[c];
        #pragma unroll 8
        for (int j = 0; j < 64; j++) d += sh[b*64 + j] * fc2w[c*64 + j];
        g_chw[t2] = 1.f / (1.f + __expf(-d));
    }
    if (tid < 256) {
        float m  = g_sum[tid]   * (1.f/32768.f);
        float vr = g_sumsq[tid] * (1.f/32768.f) - m*m;
        float sc = gamma[tid] * rsqrtf(vr + 1e-5f);
        g_bns[tid] = sc;
        g_bnb[tid] = beta[tid] - m*sc;
    }
}

// ---------------- finalize ----------------------------------------------------
__global__ void k_final(const float* __restrict__ x, float* __restrict__ out) {
    size_t i4 = (size_t)blockIdx.x*256 + threadIdx.x;
    int bc = (int)(i4 >> 10);
    int c  = bc & 255;
    float4 xv = ((const float4*)x)[i4];
    float4 ov = ((const float4*)g_out)[i4];
    float sc = g_bns[c], bb = g_bnb[c], cw = g_chw[bc];
    float4 r;
    r.x = xv.x + (ov.x*sc + bb)*cw;
    r.y = xv.y + (ov.y*sc + bb)*cw;
    r.z = xv.z + (ov.z*sc + bb)*cw;
    r.w = xv.w + (ov.w*sc + bb)*cw;
    ((float4*)out)[i4] = r;
}

// ------------------------------------------------------------------------------
extern "C" void kernel_launch(void* const* d_in, const int* in_sizes, int n_in,
                              void* d_out, int out_size) {
    const float* x     = (const float*)d_in[0];
    const float* tw    = (const float*)d_in[1];
    const float* pw    = (const float*)d_in[2];
    const float* gw    = (const float*)d_in[3];
    const float* ow    = (const float*)d_in[4];
    const float* gamma = (const float*)d_in[5];
    const float* beta  = (const float*)d_in[6];
    const float* fc1w  = (const float*)d_in[7];
    const float* fc1b  = (const float*)d_in[8];
    const float* fc2w  = (const float*)d_in[9];
    const float* fc2b  = (const float*)d_in[10];
    float* out = (float*)d_out;

    cudaFuncSetAttribute(k_proj,  cudaFuncAttributeMaxDynamicSharedMemorySize, 65536);
    cudaFuncSetAttribute(k_flash, cudaFuncAttributeMaxDynamicSharedMemorySize, 81920);

    k_zero<<<1, 256>>>();
    k_prew<<<64, 256>>>(tw, pw, gw, ow);
    k_proj<<<dim3(64, 1, BB), 256, 65536>>>(x);
    k_flash<<<dim3(64, BB), 128, 81920>>>();
    k_se<<<1, 256>>>(fc1w, fc1b, fc2w, fc2b, gamma, beta);
    k_final<<<8192, 256>>>(x, out);
}